// round 13
// baseline (speedup 1.0000x reference)
#include <cuda_runtime.h>
#include <cuda_bf16.h>
#include <cstdint>

// Problem: B=128, T=512, I=64, H=512, C=10.
#define BB 128
#define TT 512
#define II 64
#define HH 512
#define CC 10

#define NB 128        // persistent blocks, 1 per SM
#define NT 512        // 16 warps: k-split 4 x m-split 4
#define MT 64         // gate-rows per block (16 cells x 4 gates interleaved)
#define KTOT 576
#define KW 144        // k per k-partition
#define KSTEPS 9      // k16 steps per k-partition
#define RSB 1168      // padded row stride bytes (584 bf16) — conflict-free ldmatrix

// ---------------- smem layout (bytes) ----------------
#define SM_WLO   0
#define W_BYTES  (MT * RSB)                 // 74752 (W_lo resident)
#define SM_AHI   W_BYTES                    // act hi [32 x 1168] (h + x granules)
#define A_BYTES  (32 * RSB)                 // 37376
#define SM_ALO   (SM_AHI + A_BYTES)         // 112128
#define SM_PRE   (SM_ALO + A_BYTES)         // 149504 ; pre[4][64][34] floats (de-aliased)
#define PRE_STRIDE 34
#define PRE_BLK  (MT * PRE_STRIDE)          // 2176 floats per k-partition
#define SM_BIAS  (SM_PRE + 34816)           // 184320 ; 64 floats
#define SM_RED   (SM_BIAS + 256)            // classifier scratch 10*16 floats
#define SMEM_TOTAL (SM_RED + 704)           // 185280
// W_hi staged temporarily through the act region (74752 B = AHI+ALO exactly)
#define SM_WTMP  SM_AHI

// ---------------- device globals ----------------
__device__ __align__(256) __nv_bfloat16 g_x_hi[TT * BB * II];   // [t][b][i]
__device__ __align__(256) __nv_bfloat16 g_x_lo[TT * BB * II];
__device__ __align__(256) __nv_bfloat16 g_h_hi[2][BB * HH];     // [b][n]
__device__ __align__(256) __nv_bfloat16 g_h_lo[2][BB * HH];
__device__ __align__(256) float g_h32[BB * HH];
__device__ unsigned g_count = 0;
__device__ unsigned g_epoch = 0;

// ---------------- helpers ----------------
__device__ __forceinline__ uint32_t smem_u32(const void* p) {
    uint32_t a;
    asm("{ .reg .u64 t; cvta.to.shared.u64 t, %1; cvt.u32.u64 %0, t; }" : "=r"(a) : "l"(p));
    return a;
}
__device__ __forceinline__ void cp16(uint32_t dst, const void* src) {
    asm volatile("cp.async.cg.shared.global [%0], [%1], 16;" :: "r"(dst), "l"(src));
}
__device__ __forceinline__ void ldm4(uint32_t* r, uint32_t addr) {
    asm volatile("ldmatrix.sync.aligned.m8n8.x4.shared.b16 {%0,%1,%2,%3}, [%4];"
                 : "=r"(r[0]), "=r"(r[1]), "=r"(r[2]), "=r"(r[3]) : "r"(addr));
}
__device__ __forceinline__ void mma16816(float* c, const uint32_t* a, const uint32_t* b) {
    asm volatile("mma.sync.aligned.m16n8k16.row.col.f32.bf16.bf16.f32 "
                 "{%0,%1,%2,%3}, {%4,%5,%6,%7}, {%8,%9}, {%0,%1,%2,%3};"
                 : "+f"(c[0]), "+f"(c[1]), "+f"(c[2]), "+f"(c[3])
                 : "r"(a[0]), "r"(a[1]), "r"(a[2]), "r"(a[3]), "r"(b[0]), "r"(b[1]));
}
__device__ __forceinline__ float tanh_fast(float x) {
    float y; asm("tanh.approx.f32 %0, %1;" : "=f"(y) : "f"(x)); return y;
}
__device__ __forceinline__ float sigmoid_fast(float x) { return 0.5f * tanh_fast(0.5f * x) + 0.5f; }
__device__ __forceinline__ float ldcg(const float* p) {
    float v; asm volatile("ld.global.cg.f32 %0, [%1];" : "=f"(v) : "l"(p)); return v;
}

// full grid barrier: 128 co-resident blocks (R7-proven pattern)
__device__ __forceinline__ void grid_sync() {
    __threadfence();
    __syncthreads();
    if (threadIdx.x == 0) {
        unsigned e = *((volatile unsigned*)&g_epoch);
        unsigned prev = atomicAdd(&g_count, 1);
        if (prev == NB - 1) {
            g_count = 0;
            __threadfence();
            *((volatile unsigned*)&g_epoch) = e + 1;
        } else {
            while (*((volatile unsigned*)&g_epoch) == e) { __nanosleep(32); }
        }
    }
    __syncthreads();
}

// ---------------- prologue: split x into bf16 hi/lo, layout [t][b][i] ----------------
__global__ void __launch_bounds__(256) xsplit_kernel(const float* __restrict__ x) {
    int gid = blockIdx.x * 256 + threadIdx.x;       // [t][b][i]
    int i = gid & 63, b = (gid >> 6) & 127, t = gid >> 13;
    float v = x[((size_t)b * TT + t) * II + i];
    __nv_bfloat16 hi = __float2bfloat16(v);
    g_x_hi[gid] = hi;
    g_x_lo[gid] = __float2bfloat16(v - __bfloat162float(hi));
}

// ---------------- persistent LSTM (mma.sync bf16, 3-term split, W_hi in regs) ----------------
__global__ void __launch_bounds__(NT, 1)
lstm_kernel(const float* __restrict__ W_ih, const float* __restrict__ W_hh,
            const float* __restrict__ b_ih, const float* __restrict__ b_hh,
            const float* __restrict__ W_cls, const float* __restrict__ b_cls,
            float* __restrict__ out)
{
    extern __shared__ __align__(1024) char smem[];
    const uint32_t sb = smem_u32(smem);
    float* bias_s = (float*)(smem + SM_BIAS);
    float* pre    = (float*)(smem + SM_PRE);      // [4][64][34]

    const int tid  = threadIdx.x;
    const int wid  = tid >> 5;
    const int lane = tid & 31;
    const int wk   = wid & 3;           // k partition 0..3
    const int wm   = wid >> 2;          // m quarter 0..3 (rows wm*16..wm*16+15)
    const int blk  = blockIdx.x;
    const int mt   = blk >> 2;          // 32 m-groups (16 cells each)
    const int nt   = blk & 3;           // 4 batch groups (32 each)

    // ---- weight prologue: W_lo resident in smem, W_hi staged then reg-loaded ----
    for (int idx = tid; idx < MT * KTOT; idx += NT) {
        int r = idx / KTOT, k = idx - r * KTOT;
        int gate = r & 3, hidl = r >> 2;
        int grow = gate * HH + mt * 16 + hidl;
        float v = (k < HH) ? W_hh[(size_t)grow * HH + k]
                           : W_ih[(size_t)grow * II + (k - HH)];
        __nv_bfloat16 hi = __float2bfloat16(v);
        __nv_bfloat16 lo = __float2bfloat16(v - __bfloat162float(hi));
        *(__nv_bfloat16*)(smem + SM_WTMP + r * RSB + k * 2) = hi;
        *(__nv_bfloat16*)(smem + SM_WLO  + r * RSB + k * 2) = lo;
    }
    if (tid < MT) {
        int gate = tid & 3, hidl = tid >> 2;
        int grow = gate * HH + mt * 16 + hidl;
        bias_s[tid] = b_ih[grow] + b_hh[grow];
    }
    __syncthreads();

    // ldmatrix offsets (layouts validated R6/R7)
    const uint32_t a_off = (uint32_t)((lane & 15) * RSB + (lane >> 4) * 16);
    const uint32_t b_off = (uint32_t)(((lane & 7) + ((lane >> 4) << 3)) * RSB
                                      + (((lane >> 3) & 1) * 16));
    const int k0w = wk * KW;

    // W_hi fragments -> registers (constant for all 512 steps): 16 rows per warp
    uint32_t whi[KSTEPS][4];
#pragma unroll
    for (int ks = 0; ks < KSTEPS; ++ks)
        ldm4(whi[ks], sb + SM_WTMP + (uint32_t)(wm * 16) * RSB
                        + a_off + (uint32_t)((k0w + ks * 16) * 2));
    __syncthreads();   // W_hi consumed; act region free

    // zero h0 hi/lo (each block strides a distinct 512-element slice)
    {
        size_t base = (size_t)blk * NT + tid;
        g_h_hi[0][base] = __float2bfloat16(0.f);
        g_h_lo[0][base] = __float2bfloat16(0.f);
    }
    // cell state: exactly 1 cell per thread
    const int hidl_c = tid >> 5;        // 0..15
    const int b_c    = tid & 31;        // 0..31
    const int ng0 = mt * 16 + hidl_c;
    const int bg0 = nt * 32 + b_c;
    float cst = 0.f;
    float bias4[4];
#pragma unroll
    for (int gate = 0; gate < 4; ++gate) bias4[gate] = bias_s[hidl_c * 4 + gate];

    grid_sync();

    for (int t = 0; t < TT; ++t) {
        const int cur = t & 1, nxt = cur ^ 1;
        const __nv_bfloat16* hhi = g_h_hi[cur];
        const __nv_bfloat16* hlo = g_h_lo[cur];
        const __nv_bfloat16* xhi = g_x_hi + (size_t)t * (BB * II);
        const __nv_bfloat16* xlo = g_x_lo + (size_t)t * (BB * II);

        // ---- stage act hi (group 0) then act lo (group 1): block-wide, coalesced ----
        // plane = 32 rows x 72 granules (h: 0..63, x: 64..71) = 2304 granules
#pragma unroll
        for (int it = 0; it < 5; ++it) {
            int idx = tid + it * NT;
            if (idx < 2304) {
                int rb = idx / 72, gk = idx - rb * 72;
                const __nv_bfloat16* src = (gk < 64)
                    ? hhi + (size_t)(nt * 32 + rb) * HH + gk * 8
                    : xhi + (size_t)(nt * 32 + rb) * II + (gk - 64) * 8;
                cp16(sb + SM_AHI + (uint32_t)(rb * RSB + gk * 16), src);
            }
        }
        asm volatile("cp.async.commit_group;");
#pragma unroll
        for (int it = 0; it < 5; ++it) {
            int idx = tid + it * NT;
            if (idx < 2304) {
                int rb = idx / 72, gk = idx - rb * 72;
                const __nv_bfloat16* src = (gk < 64)
                    ? hlo + (size_t)(nt * 32 + rb) * HH + gk * 8
                    : xlo + (size_t)(nt * 32 + rb) * II + (gk - 64) * 8;
                cp16(sb + SM_ALO + (uint32_t)(rb * RSB + gk * 16), src);
            }
        }
        asm volatile("cp.async.commit_group;");

        float acc[4][4];
#pragma unroll
        for (int ni = 0; ni < 4; ++ni) {
            acc[ni][0] = 0.f; acc[ni][1] = 0.f; acc[ni][2] = 0.f; acc[ni][3] = 0.f;
        }

        // ---- phase 1: (W_hi + W_lo) * a_hi — overlaps a_lo staging ----
        asm volatile("cp.async.wait_group 1;");
        __syncthreads();
#pragma unroll
        for (int ks = 0; ks < KSTEPS; ++ks) {
            const uint32_t kb = (uint32_t)((k0w + ks * 16) * 2);
            uint32_t bh[2][4], al[4];
#pragma unroll
            for (int p = 0; p < 2; ++p)
                ldm4(bh[p], sb + SM_AHI + (uint32_t)(p * 16) * RSB + b_off + kb);
            ldm4(al, sb + SM_WLO + (uint32_t)(wm * 16) * RSB + a_off + kb);
#pragma unroll
            for (int ni = 0; ni < 4; ++ni) {
                const uint32_t* bf = &bh[ni >> 1][(ni & 1) * 2];
                mma16816(acc[ni], whi[ks], bf);
                mma16816(acc[ni], al, bf);
            }
        }

        // ---- phase 2: W_hi * a_lo ----
        asm volatile("cp.async.wait_group 0;");
        __syncthreads();
#pragma unroll
        for (int ks = 0; ks < KSTEPS; ++ks) {
            const uint32_t kb = (uint32_t)((k0w + ks * 16) * 2);
            uint32_t bl[2][4];
#pragma unroll
            for (int p = 0; p < 2; ++p)
                ldm4(bl[p], sb + SM_ALO + (uint32_t)(p * 16) * RSB + b_off + kb);
#pragma unroll
            for (int ni = 0; ni < 4; ++ni)
                mma16816(acc[ni], whi[ks], &bl[ni >> 1][(ni & 1) * 2]);
        }

        // ---- store k-partials (pre de-aliased: no pre-store sync needed) ----
        {
            const int g = lane >> 2, t2 = (lane & 3) * 2;
            float* pw = pre + wk * PRE_BLK;
#pragma unroll
            for (int ni = 0; ni < 4; ++ni) {
                int row = wm * 16 + g, col = ni * 8 + t2;
                *(float2*)(pw + row * PRE_STRIDE + col) =
                    make_float2(acc[ni][0], acc[ni][1]);
                *(float2*)(pw + (row + 8) * PRE_STRIDE + col) =
                    make_float2(acc[ni][2], acc[ni][3]);
            }
        }
        __syncthreads();

        // ---- reduce + gates + state update: 1 cell per thread ----
        {
            float s[4];
#pragma unroll
            for (int gate = 0; gate < 4; ++gate) {
                const int r = hidl_c * 4 + gate;
                float a = bias4[gate];
#pragma unroll
                for (int w = 0; w < 4; ++w)
                    a += pre[w * PRE_BLK + r * PRE_STRIDE + b_c];
                s[gate] = a;
            }
            float ig = sigmoid_fast(s[0]);
            float fg = sigmoid_fast(s[1]);
            float gg = tanh_fast(s[2]);
            float og = sigmoid_fast(s[3]);
            cst = fg * cst + ig * gg;
            float hv = og * tanh_fast(cst);
            __nv_bfloat16 hb = __float2bfloat16(hv);
            size_t off = (size_t)bg0 * HH + ng0;
            g_h_hi[nxt][off] = hb;
            g_h_lo[nxt][off] = __float2bfloat16(hv - __bfloat162float(hb));
            if (t == TT - 1) g_h32[off] = hv;
        }

        grid_sync();
    }

    // ---------------- classifier: block handles batch b = blk ----------------
    {
        const int b = blk;
        float h = ldcg(&g_h32[(size_t)b * HH + tid]);
        float* red = (float*)(smem + SM_RED);
#pragma unroll 1
        for (int cl = 0; cl < CC; ++cl) {
            const float* wc = W_cls + (size_t)cl * HH;
            float s = h * wc[tid];
#pragma unroll
            for (int off = 16; off; off >>= 1)
                s += __shfl_xor_sync(0xFFFFFFFFu, s, off);
            if (lane == 0) red[cl * 16 + wid] = s;
        }
        __syncthreads();
        if (tid < CC) {
            float s = 0.f;
#pragma unroll
            for (int w = 0; w < 16; ++w) s += red[tid * 16 + w];
            out[b * CC + tid] = s + b_cls[tid];
        }
    }
}

// ---------------- launch ----------------
extern "C" void kernel_launch(void* const* d_in, const int* in_sizes, int n_in,
                              void* d_out, int out_size) {
    const float* x     = (const float*)d_in[0];
    const float* W_ih  = (const float*)d_in[1];
    const float* W_hh  = (const float*)d_in[2];
    const float* b_ih  = (const float*)d_in[3];
    const float* b_hh  = (const float*)d_in[4];
    const float* W_cls = (const float*)d_in[5];
    const float* b_cls = (const float*)d_in[6];
    float* out = (float*)d_out;

    cudaFuncSetAttribute(lstm_kernel, cudaFuncAttributeMaxDynamicSharedMemorySize, SMEM_TOTAL);

    xsplit_kernel<<<(TT * BB * II) / 256, 256>>>(x);
    lstm_kernel<<<NB, NT, SMEM_TOTAL>>>(W_ih, W_hh, b_ih, b_hh, W_cls, b_cls, out);
}

// round 14
// speedup vs baseline: 1.2067x; 1.2067x over previous
#include <cuda_runtime.h>
#include <cuda_bf16.h>
#include <cstdint>

// Problem: B=128, T=512, I=64, H=512, C=10.
#define BB 128
#define TT 512
#define II 64
#define HH 512
#define CC 10

#define NB 128        // persistent blocks, 1 per SM
#define NT 256        // 8 warps: k-split 2 x m-split 4
#define MT 64         // gate-rows per block (16 cells x 4 gates interleaved)
#define KTOT 576
#define KW 288        // k per k-partition
#define KSTEPS 18     // k16 steps per k-partition
#define RSB 1168      // padded row stride bytes (584 bf16) — conflict-free ldmatrix

// ---------------- smem layout (bytes) ----------------
#define SM_WLO   0
#define W_BYTES  (MT * RSB)                 // 74752 (W_lo resident)
#define SM_AHI   W_BYTES                    // act hi [32 x 1168] (h + x granules)
#define A_BYTES  (32 * RSB)                 // 37376
#define SM_ALO   (SM_AHI + A_BYTES)         // 112128
#define SM_PRE   (SM_ALO + A_BYTES)         // 149504 ; pre[2][64][34] floats = 17408
#define PRE_STRIDE 34
#define PRE_BLK  (MT * PRE_STRIDE)          // 2176 floats per k-partition
#define SM_BIAS  (SM_PRE + 17408)           // 166912 ; 64 floats
#define SM_RED   (SM_BIAS + 256)            // classifier scratch 10*8 floats
#define SMEM_TOTAL (SM_RED + 320)           // 167488
// W_hi staged temporarily through the act region (74752 B = AHI+ALO exactly)
#define SM_WTMP  SM_AHI

// ---------------- device globals ----------------
__device__ __align__(256) __nv_bfloat16 g_x_hi[TT * BB * II];   // [t][b][i]
__device__ __align__(256) __nv_bfloat16 g_x_lo[TT * BB * II];
__device__ __align__(256) __nv_bfloat16 g_h_hi[2][BB * HH];     // [b][n]
__device__ __align__(256) __nv_bfloat16 g_h_lo[2][BB * HH];
__device__ __align__(256) float g_h32[BB * HH];
__device__ unsigned g_count = 0;
__device__ unsigned g_epoch = 0;

// ---------------- helpers ----------------
__device__ __forceinline__ uint32_t smem_u32(const void* p) {
    uint32_t a;
    asm("{ .reg .u64 t; cvta.to.shared.u64 t, %1; cvt.u32.u64 %0, t; }" : "=r"(a) : "l"(p));
    return a;
}
__device__ __forceinline__ void cp16(uint32_t dst, const void* src) {
    asm volatile("cp.async.cg.shared.global [%0], [%1], 16;" :: "r"(dst), "l"(src));
}
__device__ __forceinline__ void ldm4(uint32_t* r, uint32_t addr) {
    asm volatile("ldmatrix.sync.aligned.m8n8.x4.shared.b16 {%0,%1,%2,%3}, [%4];"
                 : "=r"(r[0]), "=r"(r[1]), "=r"(r[2]), "=r"(r[3]) : "r"(addr));
}
__device__ __forceinline__ void mma16816(float* c, const uint32_t* a, const uint32_t* b) {
    asm volatile("mma.sync.aligned.m16n8k16.row.col.f32.bf16.bf16.f32 "
                 "{%0,%1,%2,%3}, {%4,%5,%6,%7}, {%8,%9}, {%0,%1,%2,%3};"
                 : "+f"(c[0]), "+f"(c[1]), "+f"(c[2]), "+f"(c[3])
                 : "r"(a[0]), "r"(a[1]), "r"(a[2]), "r"(a[3]), "r"(b[0]), "r"(b[1]));
}
__device__ __forceinline__ float tanh_fast(float x) {
    float y; asm("tanh.approx.f32 %0, %1;" : "=f"(y) : "f"(x)); return y;
}
__device__ __forceinline__ float sigmoid_fast(float x) { return 0.5f * tanh_fast(0.5f * x) + 0.5f; }
__device__ __forceinline__ float ldcg(const float* p) {
    float v; asm volatile("ld.global.cg.f32 %0, [%1];" : "=f"(v) : "l"(p)); return v;
}

// full grid barrier: 128 co-resident blocks (R7-proven pattern, verbatim)
__device__ __forceinline__ void grid_sync() {
    __threadfence();
    __syncthreads();
    if (threadIdx.x == 0) {
        unsigned e = *((volatile unsigned*)&g_epoch);
        unsigned prev = atomicAdd(&g_count, 1);
        if (prev == NB - 1) {
            g_count = 0;
            __threadfence();
            *((volatile unsigned*)&g_epoch) = e + 1;
        } else {
            while (*((volatile unsigned*)&g_epoch) == e) { __nanosleep(32); }
        }
    }
    __syncthreads();
}

// ---------------- prologue: split x into bf16 hi/lo, layout [t][b][i] ----------------
__global__ void __launch_bounds__(256) xsplit_kernel(const float* __restrict__ x) {
    int gid = blockIdx.x * 256 + threadIdx.x;       // [t][b][i]
    int i = gid & 63, b = (gid >> 6) & 127, t = gid >> 13;
    float v = x[((size_t)b * TT + t) * II + i];
    __nv_bfloat16 hi = __float2bfloat16(v);
    g_x_hi[gid] = hi;
    g_x_lo[gid] = __float2bfloat16(v - __bfloat162float(hi));
}

// ---------------- persistent LSTM (mma.sync bf16, 3-term split, W_hi in regs) ----------------
__global__ void __launch_bounds__(NT, 1)
lstm_kernel(const float* __restrict__ W_ih, const float* __restrict__ W_hh,
            const float* __restrict__ b_ih, const float* __restrict__ b_hh,
            const float* __restrict__ W_cls, const float* __restrict__ b_cls,
            float* __restrict__ out)
{
    extern __shared__ __align__(1024) char smem[];
    const uint32_t sb = smem_u32(smem);
    float* bias_s = (float*)(smem + SM_BIAS);
    float* pre    = (float*)(smem + SM_PRE);      // [2][64][34]

    const int tid  = threadIdx.x;
    const int wid  = tid >> 5;
    const int lane = tid & 31;
    const int wk   = wid & 1;           // k partition 0..1 (K=288 each)
    const int wm   = wid >> 1;          // m quarter 0..3 (rows wm*16..wm*16+15)
    const int blk  = blockIdx.x;
    const int mt   = blk >> 2;          // 32 m-groups (16 cells each)
    const int nt   = blk & 3;           // 4 batch groups (32 each)

    // ---- weight prologue: W_lo resident in smem, W_hi staged then reg-loaded ----
    for (int idx = tid; idx < MT * KTOT; idx += NT) {
        int r = idx / KTOT, k = idx - r * KTOT;
        int gate = r & 3, hidl = r >> 2;
        int grow = gate * HH + mt * 16 + hidl;
        float v = (k < HH) ? W_hh[(size_t)grow * HH + k]
                           : W_ih[(size_t)grow * II + (k - HH)];
        __nv_bfloat16 hi = __float2bfloat16(v);
        __nv_bfloat16 lo = __float2bfloat16(v - __bfloat162float(hi));
        *(__nv_bfloat16*)(smem + SM_WTMP + r * RSB + k * 2) = hi;
        *(__nv_bfloat16*)(smem + SM_WLO  + r * RSB + k * 2) = lo;
    }
    if (tid < MT) {
        int gate = tid & 3, hidl = tid >> 2;
        int grow = gate * HH + mt * 16 + hidl;
        bias_s[tid] = b_ih[grow] + b_hh[grow];
    }
    __syncthreads();

    // ldmatrix offsets (layouts validated R6/R7)
    const uint32_t a_off = (uint32_t)((lane & 15) * RSB + (lane >> 4) * 16);
    const uint32_t b_off = (uint32_t)(((lane & 7) + ((lane >> 4) << 3)) * RSB
                                      + (((lane >> 3) & 1) * 16));
    const int k0w = wk * KW;

    // W_hi fragments -> registers (constant for all 512 steps): 16 rows x 18 ksteps
    uint32_t whi[KSTEPS][4];
#pragma unroll
    for (int ks = 0; ks < KSTEPS; ++ks)
        ldm4(whi[ks], sb + SM_WTMP + (uint32_t)(wm * 16) * RSB
                        + a_off + (uint32_t)((k0w + ks * 16) * 2));
    __syncthreads();   // W_hi consumed; act region free

    // zero h0 hi/lo (each block strides a distinct 512-element slice)
    {
        size_t base = ((size_t)blk * NT + tid) * 2;
        *(unsigned*)(&g_h_hi[0][base]) = 0u;
        *(unsigned*)(&g_h_lo[0][base]) = 0u;
    }
    // cell state: 2 cells per thread (hidl_c, batches b_c & b_c+1)
    const int hidl_c = tid >> 4;        // 0..15
    const int b_c    = (tid * 2) & 31;
    const int ng0 = mt * 16 + hidl_c;
    const int bg0 = nt * 32 + b_c;
    float cst[2] = {0.f, 0.f};
    float bias4[4];
#pragma unroll
    for (int gate = 0; gate < 4; ++gate) bias4[gate] = bias_s[hidl_c * 4 + gate];

    for (int t = 0; t < TT; ++t) {
        const int cur = t & 1, nxt = cur ^ 1;
        const __nv_bfloat16* hhi = g_h_hi[cur];
        const __nv_bfloat16* hlo = g_h_lo[cur];
        const __nv_bfloat16* xhi = g_x_hi + (size_t)t * (BB * II);
        const __nv_bfloat16* xlo = g_x_lo + (size_t)t * (BB * II);

        // ---- group 0: x planes (h-independent) — issued BEFORE the barrier ----
#pragma unroll
        for (int i = 0; i < 2; ++i) {
            int idx = tid + i * NT;             // 0..511
            int plane = idx >> 8;               // 0 = hi, 1 = lo
            int rem = idx & 255;
            int rb = rem >> 3, xg = rem & 7;    // row 0..31, x granule 0..7
            const __nv_bfloat16* src = (plane ? xlo : xhi)
                + (size_t)(nt * 32 + rb) * II + xg * 8;
            cp16(sb + (plane ? SM_ALO : SM_AHI) + (uint32_t)(rb * RSB + (64 + xg) * 16), src);
        }
        asm volatile("cp.async.commit_group;");

        // ---- barrier: h(t) from all producers is ready after this ----
        grid_sync();

        // ---- group 1: h hi ; group 2: h lo (block-wide, coalesced) ----
#pragma unroll
        for (int it = 0; it < 8; ++it) {
            int idx = tid + it * NT;            // 0..2047
            int rb = idx >> 6, gk = idx & 63;
            cp16(sb + SM_AHI + (uint32_t)(rb * RSB + gk * 16),
                 hhi + (size_t)(nt * 32 + rb) * HH + gk * 8);
        }
        asm volatile("cp.async.commit_group;");
#pragma unroll
        for (int it = 0; it < 8; ++it) {
            int idx = tid + it * NT;
            int rb = idx >> 6, gk = idx & 63;
            cp16(sb + SM_ALO + (uint32_t)(rb * RSB + gk * 16),
                 hlo + (size_t)(nt * 32 + rb) * HH + gk * 8);
        }
        asm volatile("cp.async.commit_group;");

        float acc[4][4];
#pragma unroll
        for (int ni = 0; ni < 4; ++ni) {
            acc[ni][0] = 0.f; acc[ni][1] = 0.f; acc[ni][2] = 0.f; acc[ni][3] = 0.f;
        }

        // ---- phase 1: (W_hi + W_lo) * a_hi — overlaps a_lo staging ----
        asm volatile("cp.async.wait_group 1;");   // groups 0 (x) + 1 (h hi) done
        __syncthreads();
#pragma unroll
        for (int ks = 0; ks < KSTEPS; ++ks) {
            const uint32_t kb = (uint32_t)((k0w + ks * 16) * 2);
            uint32_t bh[2][4], al[4];
#pragma unroll
            for (int p = 0; p < 2; ++p)
                ldm4(bh[p], sb + SM_AHI + (uint32_t)(p * 16) * RSB + b_off + kb);
            ldm4(al, sb + SM_WLO + (uint32_t)(wm * 16) * RSB + a_off + kb);
#pragma unroll
            for (int ni = 0; ni < 4; ++ni) {
                const uint32_t* bf = &bh[ni >> 1][(ni & 1) * 2];
                mma16816(acc[ni], whi[ks], bf);
                mma16816(acc[ni], al, bf);
            }
        }

        // ---- phase 2: W_hi * a_lo ----
        asm volatile("cp.async.wait_group 0;");
        __syncthreads();
#pragma unroll
        for (int ks = 0; ks < KSTEPS; ++ks) {
            const uint32_t kb = (uint32_t)((k0w + ks * 16) * 2);
            uint32_t bl[2][4];
#pragma unroll
            for (int p = 0; p < 2; ++p)
                ldm4(bl[p], sb + SM_ALO + (uint32_t)(p * 16) * RSB + b_off + kb);
#pragma unroll
            for (int ni = 0; ni < 4; ++ni)
                mma16816(acc[ni], whi[ks], &bl[ni >> 1][(ni & 1) * 2]);
        }

        // ---- store k-partials (pre de-aliased: no pre-store sync needed) ----
        {
            const int g = lane >> 2, t2 = (lane & 3) * 2;
            float* pw = pre + wk * PRE_BLK;
#pragma unroll
            for (int ni = 0; ni < 4; ++ni) {
                int row = wm * 16 + g, col = ni * 8 + t2;
                *(float2*)(pw + row * PRE_STRIDE + col) =
                    make_float2(acc[ni][0], acc[ni][1]);
                *(float2*)(pw + (row + 8) * PRE_STRIDE + col) =
                    make_float2(acc[ni][2], acc[ni][3]);
            }
        }
        __syncthreads();

        // ---- reduce (2 planes) + gates + state update: 2 cells per thread ----
        {
            float2 s2[4];
#pragma unroll
            for (int gate = 0; gate < 4; ++gate) {
                const int r = hidl_c * 4 + gate;
                float2 a = make_float2(bias4[gate], bias4[gate]);
#pragma unroll
                for (int w = 0; w < 2; ++w) {
                    float2 p2 = *(const float2*)(pre + w * PRE_BLK + r * PRE_STRIDE + b_c);
                    a.x += p2.x; a.y += p2.y;
                }
                s2[gate] = a;
            }
#pragma unroll
            for (int j = 0; j < 2; ++j) {
                float si = j ? s2[0].y : s2[0].x;
                float sf = j ? s2[1].y : s2[1].x;
                float sg = j ? s2[2].y : s2[2].x;
                float so = j ? s2[3].y : s2[3].x;
                float ig = sigmoid_fast(si);
                float fg = sigmoid_fast(sf);
                float gg = tanh_fast(sg);
                float og = sigmoid_fast(so);
                cst[j] = fg * cst[j] + ig * gg;
                float hv = og * tanh_fast(cst[j]);
                __nv_bfloat16 hb = __float2bfloat16(hv);
                size_t off = (size_t)(bg0 + j) * HH + ng0;
                g_h_hi[nxt][off] = hb;
                g_h_lo[nxt][off] = __float2bfloat16(hv - __bfloat162float(hb));
                if (t == TT - 1) g_h32[off] = hv;
            }
        }
    }

    // ---- settle: all blocks finished final h write ----
    grid_sync();

    // ---------------- classifier: block handles batch b = blk ----------------
    {
        const int b = blk;
        float h[2];
#pragma unroll
        for (int p = 0; p < 2; ++p)
            h[p] = ldcg(&g_h32[(size_t)b * HH + tid + p * NT]);
        float* red = (float*)(smem + SM_RED);
#pragma unroll 1
        for (int cl = 0; cl < CC; ++cl) {
            const float* wc = W_cls + (size_t)cl * HH;
            float s = h[0] * wc[tid] + h[1] * wc[tid + NT];
#pragma unroll
            for (int off = 16; off; off >>= 1)
                s += __shfl_xor_sync(0xFFFFFFFFu, s, off);
            if (lane == 0) red[cl * 8 + wid] = s;
        }
        __syncthreads();
        if (tid < CC) {
            float s = 0.f;
#pragma unroll
            for (int w = 0; w < 8; ++w) s += red[tid * 8 + w];
            out[b * CC + tid] = s + b_cls[tid];
        }
    }
}

// ---------------- launch ----------------
extern "C" void kernel_launch(void* const* d_in, const int* in_sizes, int n_in,
                              void* d_out, int out_size) {
    const float* x     = (const float*)d_in[0];
    const float* W_ih  = (const float*)d_in[1];
    const float* W_hh  = (const float*)d_in[2];
    const float* b_ih  = (const float*)d_in[3];
    const float* b_hh  = (const float*)d_in[4];
    const float* W_cls = (const float*)d_in[5];
    const float* b_cls = (const float*)d_in[6];
    float* out = (float*)d_out;

    cudaFuncSetAttribute(lstm_kernel, cudaFuncAttributeMaxDynamicSharedMemorySize, SMEM_TOTAL);

    xsplit_kernel<<<(TT * BB * II) / 256, 256>>>(x);
    lstm_kernel<<<NB, NT, SMEM_TOTAL>>>(W_ih, W_hh, b_ih, b_hh, W_cls, b_cls, out);
}